// round 14
// baseline (speedup 1.0000x reference)
#include <cuda_runtime.h>
#include <stdint.h>
#include <stddef.h>

// SparkFieldNet single step, bit-matching JAX threefry-2x32 RNG
// (jax_threefry_partitionable scheme).
// Inputs: 0=W[N*N] f32, 1=s[N] f32, 2=M[N] f32, 3=spark_pos[K] i32,
//         4=spark_energy[K] f32, 5=spark_age[K] i32
// Output: concat(pos[K], W[N*N], s[N], M[N], energy[K], age[K]) as float32.

#define N 8192
#define K 256
#define TOPT 32
#define BIT_DEP (1 << 16)
#define BIT_LST (1 << 17)
#define SCAN_T 544    /* 17 warps: warp0 = decision, warps1..16 = 512 A-threads */

extern "C" __device__ float __nv_logf(float);

typedef unsigned long long u64;

// ---- device scratch ----
__device__ float2 g_gd[(size_t)K * N];   // {gumbel, div} per spark x pos (16MB)
__device__ float  g_Wc[(size_t)N * 256]; // W[:, 0:256] compact copy (8MB)
__device__ u64    g_top[(size_t)K * TOPT];
__device__ float  g_sState[N];
__device__ float  g_Mdec[N];
__device__ int    g_forced[N];
__device__ unsigned g_kc0[K], g_kc1[K];
__device__ int    g_explore[K];
__device__ int    g_randpos[K];

// ---------------- Threefry-2x32 (JAX-exact, 20 rounds) ----------------
__device__ __forceinline__ void tf2x32(unsigned k0, unsigned k1,
                                       unsigned x0, unsigned x1,
                                       unsigned& o0, unsigned& o1) {
  unsigned ks2 = k0 ^ k1 ^ 0x1BD11BDAu;
  x0 += k0; x1 += k1;
#define TFR(r) { x0 += x1; x1 = (x1 << (r)) | (x1 >> (32 - (r))); x1 ^= x0; }
  TFR(13) TFR(15) TFR(26) TFR(6)   x0 += k1;  x1 += ks2 + 1u;
  TFR(17) TFR(29) TFR(16) TFR(24)  x0 += ks2; x1 += k0 + 2u;
  TFR(13) TFR(15) TFR(26) TFR(6)   x0 += k0;  x1 += k1 + 3u;
  TFR(17) TFR(29) TFR(16) TFR(24)  x0 += k1;  x1 += ks2 + 4u;
  TFR(13) TFR(15) TFR(26) TFR(6)   x0 += ks2; x1 += k0 + 5u;
#undef TFR
  o0 = x0; o1 = x1;
}

__device__ __forceinline__ void keypair(unsigned k0, unsigned k1, unsigned i,
                                        unsigned& o0, unsigned& o1) {
  tf2x32(k0, k1, 0u, i, o0, o1);
}

__device__ __forceinline__ unsigned bits32(unsigned k0, unsigned k1, unsigned j) {
  unsigned o0, o1;
  tf2x32(k0, k1, 0u, j, o0, o1);
  return o0 ^ o1;
}

__device__ __forceinline__ float f01(unsigned b) {
  return __fadd_rn(__uint_as_float((b >> 9) | 0x3f800000u), -1.0f);
}

__device__ __forceinline__ u64 packz(float z, int j) {
  unsigned zu = __float_as_uint(z);
  zu = (zu & 0x80000000u) ? ~zu : (zu | 0x80000000u);
  return ((u64)zu << 32) | (unsigned)(N - 1 - j);   // tie -> smaller index wins
}

__device__ __forceinline__ float divf(float w) {
  return __fdiv_rn(__fadd_rn(fmaxf(w, 0.0f), 1e-6f), 0.3f);
}

__device__ __forceinline__ float zf(float g, float dv, float m) {
  return __fadd_rn(g, __fadd_rn(dv, __fmul_rn(0.8f, m)));
}

// XLA ErfInv f32 polynomial (Giles)
__device__ __forceinline__ float erfinv_xla(float x) {
  float w = -log1pf(-__fmul_rn(x, x));
  float p;
  if (w < 5.0f) {
    w = w - 2.5f;
    p = 2.81022636e-08f;
    p = fmaf(p, w, 3.43273939e-07f);
    p = fmaf(p, w, -3.5233877e-06f);
    p = fmaf(p, w, -4.39150654e-06f);
    p = fmaf(p, w, 0.00021858087f);
    p = fmaf(p, w, -0.00125372503f);
    p = fmaf(p, w, -0.00417768164f);
    p = fmaf(p, w, 0.246640727f);
    p = fmaf(p, w, 1.50140941f);
  } else {
    w = sqrtf(w) - 3.0f;
    p = -0.000200214257f;
    p = fmaf(p, w, 0.000100950558f);
    p = fmaf(p, w, 0.00134934322f);
    p = fmaf(p, w, -0.00367342844f);
    p = fmaf(p, w, 0.00573950773f);
    p = fmaf(p, w, -0.0076224613f);
    p = fmaf(p, w, 0.00943887047f);
    p = fmaf(p, w, 1.00167406f);
    p = fmaf(p, w, 2.83297682f);
  }
  return p * x;
}

// ---------------- kInit: forced mask, M decay, per-spark keys --------------
__global__ void __launch_bounds__(256) kInit(const float* __restrict__ M_in,
                                             const int* __restrict__ spark_pos,
                                             const int* __restrict__ spark_age) {
  int t = threadIdx.x;
  for (int j = t; j < N; j += 256) {
    g_forced[j] = 0;
    g_Mdec[j] = __fmul_rn(M_in[j], 0.95f);
  }
  __syncthreads();

  const unsigned B0 = 0u, B1 = 42u;
  unsigned kexp0, kexp1, krand0, krand1, kcat0, kcat1;
  keypair(B0, B1, 1u, kexp0, kexp1);
  keypair(B0, B1, 2u, krand0, krand1);
  keypair(B0, B1, 3u, kcat0, kcat1);

  int i = t;
  unsigned ke0, ke1;
  keypair(kexp0, kexp1, (unsigned)i, ke0, ke1);
  g_explore[i] = (f01(bits32(ke0, ke1, 0u)) < 0.05f) ? 1 : 0;
  unsigned kr0, kr1, k20, k21;
  keypair(krand0, krand1, (unsigned)i, kr0, kr1);
  keypair(kr0, kr1, 1u, k20, k21);
  g_randpos[i] = (int)(bits32(k20, k21, 0u) & (unsigned)(N - 1));
  unsigned kc0, kc1;
  keypair(kcat0, kcat1, (unsigned)i, kc0, kc1);
  g_kc0[i] = kc0;
  g_kc1[i] = kc1;
  if (spark_age[i] < 5) g_forced[spark_pos[i]] = 1;
}

// ---------------- kMV: matvec + W decay/clip + Wc copy + state -------------
__global__ void __launch_bounds__(256) kMV(const float* __restrict__ W,
                                           const float* __restrict__ s_in,
                                           float* __restrict__ outW) {
  int r = blockIdx.x;
  const float4* w4 = (const float4*)(W + (size_t)r * N);
  const float4* s4 = (const float4*)s_in;
  float4* o4 = (float4*)(outW + (size_t)r * N);
  float4* wc4 = (float4*)(g_Wc + (size_t)r * 256);
  float acc = 0.f;
  for (int k = threadIdx.x; k < N / 4; k += 256) {
    float4 w = w4[k];
    float4 sv = s4[k];
    acc += w.x * (sv.x * 0.95f) + w.y * (sv.y * 0.95f)
         + w.z * (sv.z * 0.95f) + w.w * (sv.w * 0.95f);
    if (k < 64) wc4[k] = w;                 // original W[:,0:256] slice
    float4 o;
    o.x = fminf(fmaxf(__fmul_rn(w.x, 0.999f), -2.f), 2.f);
    o.y = fminf(fmaxf(__fmul_rn(w.y, 0.999f), -2.f), 2.f);
    o.z = fminf(fmaxf(__fmul_rn(w.z, 0.999f), -2.f), 2.f);
    o.w = fminf(fmaxf(__fmul_rn(w.w, 0.999f), -2.f), 2.f);
    o4[k] = o;
  }
  for (int off = 16; off; off >>= 1) acc += __shfl_down_sync(0xffffffffu, acc, off);
  __shared__ float sred[8];
  if ((threadIdx.x & 31) == 0) sred[threadIdx.x >> 5] = acc;
  __syncthreads();
  if (threadIdx.x == 0) {
    float a = 0.f;
    for (int w = 0; w < 8; w++) a += sred[w];
    // fused state update: noise -> sigmoid -> forced
    const unsigned B0 = 0u, B1 = 42u;
    unsigned n0, n1;
    keypair(B0, B1, 0u, n0, n1);
    const float LO = __int_as_float(0xBF7FFFFF);
    const float SQ2 = __int_as_float(0x3FB504F3);
    float f = f01(bits32(n0, n1, (unsigned)r));
    float u = fmaxf(LO, __fadd_rn(__fmul_rn(f, 2.0f), LO));
    float nrm = __fmul_rn(SQ2, erfinv_xla(u));
    float noise = __fmul_rn(0.05f, nrm);
    float x = __fadd_rn(a, noise);
    g_sState[r] = g_forced[r] ? 1.0f : (1.0f / (1.0f + expf(-x)));
  }
}

// ---------------- kGum: gumbels + {g,dv} store + top-32 selection ----------
__global__ void __launch_bounds__(1024) kGum(const float* __restrict__ W,
                                             const int* __restrict__ spark_pos) {
  extern __shared__ u64 sm_keys[];          // N keys = 64KB
  __shared__ u64 sm_red[32];
  __shared__ u64 sm_win;
  int i = blockIdx.x;
  int row = spark_pos[i];
  unsigned kc0 = g_kc0[i], kc1 = g_kc1[i];
  const float* wrow = W + (size_t)row * N;
  size_t base = (size_t)i * N;
  int tid = threadIdx.x;

  for (int j = tid; j < N; j += 1024) {
    unsigned b = bits32(kc0, kc1, (unsigned)j);
    float u = fmaxf(f01(b), 1.17549435e-38f);
    float g = -__nv_logf(-__nv_logf(u));
    float dv = divf(wrow[j]);
    float z0 = zf(g, dv, g_Mdec[j]);
    g_gd[base + j] = make_float2(g, dv);
    sm_keys[j] = packz(z0, j);
  }
  __syncthreads();

  u64 tmax = 0;
  #pragma unroll
  for (int t = 0; t < 8; t++) {
    u64 k = sm_keys[tid + t * 1024];
    if (k > tmax) tmax = k;
  }
  for (int rd = 0; rd < TOPT; rd++) {
    u64 v = tmax;
    for (int o = 16; o; o >>= 1) {
      u64 x = __shfl_down_sync(0xffffffffu, v, o);
      if (x > v) v = x;
    }
    if ((tid & 31) == 0) sm_red[tid >> 5] = v;
    __syncthreads();
    if (tid < 32) {
      u64 w = sm_red[tid];
      for (int o = 16; o; o >>= 1) {
        u64 x = __shfl_down_sync(0xffffffffu, w, o);
        if (x > w) w = x;
      }
      if (tid == 0) { sm_win = w; g_top[(size_t)i * TOPT + rd] = w; }
    }
    __syncthreads();
    u64 w = sm_win;
    if (tmax == w) {     // unique owner (keys unique)
      tmax = 0;
      #pragma unroll
      for (int t = 0; t < 8; t++) {
        int j = tid + t * 1024;
        u64 kk = sm_keys[j];
        if (kk == w) { sm_keys[j] = 0; kk = 0; }
        if (kk > tmax) tmax = kk;
      }
    }
  }
}

// ---------------- kScan: A||B pipelined serial scan, 1 barrier/iter --------
// smem: s[N] M[N] pnew[N] c[N] (128KB) + top[K*32] (64KB) + small
#define SMEM_SCAN (4 * N * 4 + K * TOPT * 8 + 2 * 16 * 8 + 512 * 4 + 10 * K * 4 + 2 * 12 * 4 + 64)

__global__ void __launch_bounds__(SCAN_T) kScan(const float* __restrict__ W,
                                                const int* __restrict__ sp,
                                                const float* __restrict__ se,
                                                const int* __restrict__ sa,
                                                float* __restrict__ out) {
  extern __shared__ __align__(16) unsigned char smraw[];
  float* s_sh = (float*)smraw;
  float* M_sh = s_sh + N;
  float* pnew = M_sh + N;
  int*   c_sh = (int*)(pnew + N);
  u64*   red = (u64*)(c_sh + N);      // [2][16]
  int*   dlist = (int*)(red + 32);    // 512
  int*   sp_sh = dlist + 512;         // K
  int*   ex_sh = sp_sh + K;
  int*   rp_sh = ex_sh + K;
  float* edec_sh = (float*)(rp_sh + K);
  int*   reset_sh = (int*)(edec_sh + K);
  int*   res_pos = reset_sh + K;
  float* res_e = (float*)(res_pos + K);
  int*   res_age = (int*)(res_e + K);
  int*   stg = res_age + K;           // [2][12] stage: parity double buffer
  u64*   top_sh = (u64*)(((char*)(stg + 24)) + ((16 - (((size_t)(stg + 24)) & 15)) & 15));

  int tid = threadIdx.x;
  int lane = tid & 31;
  int wid = tid >> 5;
  const unsigned FULL = 0xffffffffu;

  for (int j = tid; j < N; j += SCAN_T) {
    s_sh[j] = g_sState[j];
    M_sh[j] = g_Mdec[j];
    c_sh[j] = 0;
    pnew[j] = 0.f;
  }
  for (int t = tid; t < K * TOPT; t += SCAN_T) top_sh[t] = g_top[t];
  if (tid < 32) red[tid] = 0;
  for (int i2 = tid; i2 < K; i2 += SCAN_T) {
    sp_sh[i2] = sp[i2];
    ex_sh[i2] = g_explore[i2];
    rp_sh[i2] = g_randpos[i2];
    float e = __fmul_rn(se[i2], 0.98f);
    int rs = (e < 0.05f) ? 1 : 0;
    edec_sh[i2] = e;
    reset_sh[i2] = rs;
    res_e[i2] = rs ? 1.0f : e;
    res_age[i2] = rs ? 0 : (sa[i2] + 1);
    res_pos[i2] = i2;                  // reset value (i % N == i for i<256)
  }
  __syncthreads();

  int nd = 0;
  for (int t = 0; t < K; t++) {
    // ---- commit stage from B_{t-1} (all threads, same-value writes) ----
    int fx0 = -1, fx1 = -1;
    if (t > 0) {
      int* sg = stg + ((t - 1) & 1) * 12;
      int sprev = sg[0], snxt = sg[1];
      pnew[sprev] = __int_as_float(sg[7]);
      c_sh[sprev] = sg[2];
      M_sh[snxt]  = __int_as_float(sg[8]);
      c_sh[snxt]  = sg[3];
      s_sh[snxt]  = __int_as_float(sg[9]);
      int a0 = sg[4], a1 = sg[5], ndn = sg[6];
      if (a0 >= 0) dlist[ndn - ((a1 >= 0) ? 2 : 1)] = a0;
      if (a1 >= 0) dlist[ndn - 1] = a1;
      nd = ndn;
      fx0 = sprev; fx1 = snxt;
    }

    if (wid > 0) {
      // ==== A: speculative dirty-scan for spark t+1 (exact except
      //         B_t's two updates: deposit@nxt_t stale-low, patch@sp[t] skipped)
      if (t + 1 < K) {
        int atid = tid - 32;       // 0..511
        u64 pk = 0;
        if (atid < nd) {
          int idx = dlist[atid];
          if (idx != sp_sh[t]) {
            int rn = sp_sh[t + 1];
            int c = c_sh[idx];
            float2 gd = g_gd[(size_t)(t + 1) * N + idx];
            float dv = ((c & 0xffff) == (rn + 1)) ? divf(pnew[idx]) : gd.y;
            pk = packz(zf(gd.x, dv, M_sh[idx]), idx);
          }
        }
        for (int o = 16; o; o >>= 1) {
          u64 v = __shfl_down_sync(FULL, pk, o);
          if (v > pk) pk = v;
        }
        if (lane == 0) red[((t + 1) & 1) * 16 + (wid - 1)] = pk;
      }
    } else {
      // ==== B: decision for spark t ====
      int r = sp_sh[t];
      int rp = rp_sh[t];
      u64 cnd = top_sh[t * TOPT + lane];   // sorted desc
      int cidx = (N - 1) - (int)(unsigned)(cnd & 0xffffffffu);
      float wc = 0.f, wrp = 0.f;
      if (r < 256) {
        wc = g_Wc[(size_t)cidx * 256 + r];
        if (lane == 0) wrp = g_Wc[(size_t)rp * 256 + r];
      }
      // fixup: recompute exactly at B_{t-1}'s two positions (post-commit)
      u64 fmax = 0;
      int fx = (lane == 0) ? fx0 : ((lane == 1) ? fx1 : -1);
      if (fx >= 0) {
        int c = c_sh[fx];
        float2 gd = g_gd[(size_t)t * N + fx];
        float dv = ((c & 0xffff) == (r + 1)) ? divf(pnew[fx]) : gd.y;
        fmax = packz(zf(gd.x, dv, M_sh[fx]), fx);
      }
      u64 dmax = (lane < 16) ? red[(t & 1) * 16 + lane] : 0;
      if (fmax > dmax) dmax = fmax;
      for (int o = 16; o; o >>= 1) {
        u64 v = __shfl_xor_sync(FULL, dmax, o);
        if (v > dmax) dmax = v;
      }
      bool clean = !(c_sh[cidx] & BIT_LST);
      unsigned mk = __ballot_sync(FULL, clean);
      int Lwin = mk ? (__ffs(mk) - 1) : 0;
      u64 best;
      bool cleanWin = false;
      if (mk) {
        u64 bc = __shfl_sync(FULL, cnd, Lwin);
        if (dmax > bc) { best = dmax; } else { best = bc; cleanWin = true; }
      } else {
        u64 last = __shfl_sync(FULL, cnd, TOPT - 1);
        if (dmax > last) {
          best = dmax;                     // clean max <= last < dmax
        } else {
          // exact full-row fallback on current (post-B_{t-1}) state
          u64 fb = 0;
          for (int j = lane; j < N; j += 32) {
            int c = c_sh[j];
            float2 gd = g_gd[(size_t)t * N + j];
            float dv = ((c & 0xffff) == (r + 1)) ? divf(pnew[j]) : gd.y;
            u64 p2 = packz(zf(gd.x, dv, M_sh[j]), j);
            if (p2 > fb) fb = p2;
          }
          for (int o = 16; o; o >>= 1) {
            u64 v = __shfl_xor_sync(FULL, fb, o);
            if (v > fb) fb = v;
          }
          best = fb;
        }
      }
      float wcL = __shfl_sync(FULL, wc, Lwin);

      if (lane == 0) {
        int cat = (N - 1) - (int)(unsigned)(best & 0xffffffffu);
        int ex = ex_sh[t];
        int nxt = ex ? rp : cat;
        int prev = r;
        int cp = c_sh[prev];
        float wold;
        if ((cp & 0xffff) == (nxt + 1)) {
          wold = pnew[prev];
        } else if (ex) {
          wold = (prev < 256) ? wrp : W[(size_t)nxt * N + prev];
        } else if (cleanWin) {
          wold = (prev < 256) ? wcL : W[(size_t)nxt * N + prev];
        } else {
          wold = (prev < 256) ? g_Wc[(size_t)nxt * 256 + prev]
                              : W[(size_t)nxt * N + prev];
        }
        float pv = __fadd_rn(__fmul_rn(wold, 0.95f),
                             __fmul_rn(s_sh[prev], 0.05f));
        int ndn = nd;
        int a0 = -1, a1 = -1;
        int ncp = (cp & ~0xffff) | (nxt + 1);
        if (!(cp & BIT_LST)) { a0 = prev; ndn++; ncp |= BIT_LST; }
        int cn = (nxt == prev) ? ncp : c_sh[nxt];
        float Mv = __fadd_rn(M_sh[nxt], 0.2f);
        int ncn = cn | BIT_DEP;
        if (!(cn & BIT_LST)) { a1 = nxt; ndn++; ncn |= BIT_LST; }
        // stage the updates (committed by all threads next slot)
        int* sg = stg + (t & 1) * 12;
        sg[0] = prev; sg[1] = nxt; sg[2] = ncp; sg[3] = ncn;
        sg[4] = a0; sg[5] = a1; sg[6] = ndn;
        sg[7] = __float_as_int(pv);
        sg[8] = __float_as_int(Mv);
        sg[9] = __float_as_int(edec_sh[t]);
        if (!reset_sh[t]) res_pos[t] = nxt;
      }
    }
    __syncthreads();
  }

  // final commit of B_{K-1} (all threads, same values; dlist not needed)
  {
    int* sg = stg + ((K - 1) & 1) * 12;
    int sprev = sg[0], snxt = sg[1];
    pnew[sprev] = __int_as_float(sg[7]);
    c_sh[sprev] = sg[2];
    M_sh[snxt]  = __int_as_float(sg[8]);
    c_sh[snxt]  = sg[3];
    s_sh[snxt]  = __int_as_float(sg[9]);
  }
  __syncthreads();

  // epilogue: outputs (layout: pos[K], W[N*N], s[N], M[N], energy[K], age[K])
  const size_t OUT_W = K;
  const size_t OUT_S = OUT_W + (size_t)N * N;
  const size_t OUT_M = OUT_S + N;
  const size_t OUT_E = OUT_M + N;
  const size_t OUT_A = OUT_E + K;
  for (int j = tid; j < N; j += SCAN_T) {
    out[OUT_S + j] = s_sh[j];
    out[OUT_M + j] = M_sh[j];
    int c = c_sh[j];
    int prow = c & 0xffff;
    if (prow) {
      size_t idx = (size_t)(prow - 1) * N + (size_t)j;
      out[OUT_W + idx] = fminf(fmaxf(__fmul_rn(pnew[j], 0.999f), -2.f), 2.f);
    }
  }
  for (int i2 = tid; i2 < K; i2 += SCAN_T) {
    out[i2] = (float)res_pos[i2];
    out[OUT_E + i2] = res_e[i2];
    out[OUT_A + i2] = (float)res_age[i2];
  }
}

// ---------------- launch ----------------
extern "C" void kernel_launch(void* const* d_in, const int* in_sizes, int n_in,
                              void* d_out, int out_size) {
  const float* W = (const float*)d_in[0];
  const float* s = (const float*)d_in[1];
  const float* M = (const float*)d_in[2];
  const int* sp = (const int*)d_in[3];
  const float* se = (const float*)d_in[4];
  const int* sa = (const int*)d_in[5];
  float* out = (float*)d_out;

  cudaFuncSetAttribute(kGum, cudaFuncAttributeMaxDynamicSharedMemorySize,
                       N * 8);
  cudaFuncSetAttribute(kScan, cudaFuncAttributeMaxDynamicSharedMemorySize,
                       SMEM_SCAN);

  kInit<<<1, 256>>>(M, sp, sa);
  kMV<<<N, 256>>>(W, s, out + K);      // out_W starts right after pos[K]
  kGum<<<K, 1024, N * 8>>>(W, sp);
  kScan<<<1, SCAN_T, SMEM_SCAN>>>(W, sp, se, sa, out);
}

// round 15
// speedup vs baseline: 1.0711x; 1.0711x over previous
#include <cuda_runtime.h>
#include <stdint.h>
#include <stddef.h>

// SparkFieldNet single step, bit-matching JAX threefry-2x32 RNG
// (jax_threefry_partitionable scheme).
// Inputs: 0=W[N*N] f32, 1=s[N] f32, 2=M[N] f32, 3=spark_pos[K] i32,
//         4=spark_energy[K] f32, 5=spark_age[K] i32
// Output: concat(pos[K], W[N*N], s[N], M[N], energy[K], age[K]) as float32.

#define N 8192
#define K 256
#define TOPT 32
#define BIT_DEP (1 << 16)
#define BIT_LST (1 << 17)
#define SCAN_T 544    /* 17 warps: warp0 = decision, warps1..16 = 512 A-threads */

extern "C" __device__ float __nv_logf(float);

typedef unsigned long long u64;

// ---- device scratch ----
__device__ float2 g_gd[(size_t)K * N];   // {gumbel, div} per spark x pos (16MB)
__device__ float  g_Wc[(size_t)N * 256]; // W[:, 0:256] compact copy (8MB)
__device__ u64    g_top[(size_t)K * TOPT];
__device__ float  g_wold[(size_t)K * 33]; // W[cand, sp_i] for top32 + randpos
__device__ float  g_sState[N];
__device__ float  g_Mdec[N];
__device__ int    g_forced[N];
__device__ unsigned g_kc0[K], g_kc1[K];
__device__ int    g_explore[K];
__device__ int    g_randpos[K];

// ---------------- Threefry-2x32 (JAX-exact, 20 rounds) ----------------
__device__ __forceinline__ void tf2x32(unsigned k0, unsigned k1,
                                       unsigned x0, unsigned x1,
                                       unsigned& o0, unsigned& o1) {
  unsigned ks2 = k0 ^ k1 ^ 0x1BD11BDAu;
  x0 += k0; x1 += k1;
#define TFR(r) { x0 += x1; x1 = (x1 << (r)) | (x1 >> (32 - (r))); x1 ^= x0; }
  TFR(13) TFR(15) TFR(26) TFR(6)   x0 += k1;  x1 += ks2 + 1u;
  TFR(17) TFR(29) TFR(16) TFR(24)  x0 += ks2; x1 += k0 + 2u;
  TFR(13) TFR(15) TFR(26) TFR(6)   x0 += k0;  x1 += k1 + 3u;
  TFR(17) TFR(29) TFR(16) TFR(24)  x0 += k1;  x1 += ks2 + 4u;
  TFR(13) TFR(15) TFR(26) TFR(6)   x0 += ks2; x1 += k0 + 5u;
#undef TFR
  o0 = x0; o1 = x1;
}

__device__ __forceinline__ void keypair(unsigned k0, unsigned k1, unsigned i,
                                        unsigned& o0, unsigned& o1) {
  tf2x32(k0, k1, 0u, i, o0, o1);
}

__device__ __forceinline__ unsigned bits32(unsigned k0, unsigned k1, unsigned j) {
  unsigned o0, o1;
  tf2x32(k0, k1, 0u, j, o0, o1);
  return o0 ^ o1;
}

__device__ __forceinline__ float f01(unsigned b) {
  return __fadd_rn(__uint_as_float((b >> 9) | 0x3f800000u), -1.0f);
}

__device__ __forceinline__ u64 packz(float z, int j) {
  unsigned zu = __float_as_uint(z);
  zu = (zu & 0x80000000u) ? ~zu : (zu | 0x80000000u);
  return ((u64)zu << 32) | (unsigned)(N - 1 - j);   // tie -> smaller index wins
}

__device__ __forceinline__ float divf(float w) {
  return __fdiv_rn(__fadd_rn(fmaxf(w, 0.0f), 1e-6f), 0.3f);
}

__device__ __forceinline__ float zf(float g, float dv, float m) {
  return __fadd_rn(g, __fadd_rn(dv, __fmul_rn(0.8f, m)));
}

// XLA ErfInv f32 polynomial (Giles)
__device__ __forceinline__ float erfinv_xla(float x) {
  float w = -log1pf(-__fmul_rn(x, x));
  float p;
  if (w < 5.0f) {
    w = w - 2.5f;
    p = 2.81022636e-08f;
    p = fmaf(p, w, 3.43273939e-07f);
    p = fmaf(p, w, -3.5233877e-06f);
    p = fmaf(p, w, -4.39150654e-06f);
    p = fmaf(p, w, 0.00021858087f);
    p = fmaf(p, w, -0.00125372503f);
    p = fmaf(p, w, -0.00417768164f);
    p = fmaf(p, w, 0.246640727f);
    p = fmaf(p, w, 1.50140941f);
  } else {
    w = sqrtf(w) - 3.0f;
    p = -0.000200214257f;
    p = fmaf(p, w, 0.000100950558f);
    p = fmaf(p, w, 0.00134934322f);
    p = fmaf(p, w, -0.00367342844f);
    p = fmaf(p, w, 0.00573950773f);
    p = fmaf(p, w, -0.0076224613f);
    p = fmaf(p, w, 0.00943887047f);
    p = fmaf(p, w, 1.00167406f);
    p = fmaf(p, w, 2.83297682f);
  }
  return p * x;
}

// ---------------- kInit: forced mask, M decay, per-spark keys --------------
__global__ void __launch_bounds__(256) kInit(const float* __restrict__ M_in,
                                             const int* __restrict__ spark_pos,
                                             const int* __restrict__ spark_age) {
  int t = threadIdx.x;
  for (int j = t; j < N; j += 256) {
    g_forced[j] = 0;
    g_Mdec[j] = __fmul_rn(M_in[j], 0.95f);
  }
  __syncthreads();

  const unsigned B0 = 0u, B1 = 42u;
  unsigned kexp0, kexp1, krand0, krand1, kcat0, kcat1;
  keypair(B0, B1, 1u, kexp0, kexp1);
  keypair(B0, B1, 2u, krand0, krand1);
  keypair(B0, B1, 3u, kcat0, kcat1);

  int i = t;
  unsigned ke0, ke1;
  keypair(kexp0, kexp1, (unsigned)i, ke0, ke1);
  g_explore[i] = (f01(bits32(ke0, ke1, 0u)) < 0.05f) ? 1 : 0;
  unsigned kr0, kr1, k20, k21;
  keypair(krand0, krand1, (unsigned)i, kr0, kr1);
  keypair(kr0, kr1, 1u, k20, k21);
  g_randpos[i] = (int)(bits32(k20, k21, 0u) & (unsigned)(N - 1));
  unsigned kc0, kc1;
  keypair(kcat0, kcat1, (unsigned)i, kc0, kc1);
  g_kc0[i] = kc0;
  g_kc1[i] = kc1;
  if (spark_age[i] < 5) g_forced[spark_pos[i]] = 1;
}

// ---------------- kMV: matvec + W decay/clip + Wc copy + state -------------
__global__ void __launch_bounds__(256) kMV(const float* __restrict__ W,
                                           const float* __restrict__ s_in,
                                           float* __restrict__ outW) {
  int r = blockIdx.x;
  const float4* w4 = (const float4*)(W + (size_t)r * N);
  const float4* s4 = (const float4*)s_in;
  float4* o4 = (float4*)(outW + (size_t)r * N);
  float4* wc4 = (float4*)(g_Wc + (size_t)r * 256);
  float acc = 0.f;
  for (int k = threadIdx.x; k < N / 4; k += 256) {
    float4 w = w4[k];
    float4 sv = s4[k];
    acc += w.x * (sv.x * 0.95f) + w.y * (sv.y * 0.95f)
         + w.z * (sv.z * 0.95f) + w.w * (sv.w * 0.95f);
    if (k < 64) wc4[k] = w;                 // original W[:,0:256] slice
    float4 o;
    o.x = fminf(fmaxf(__fmul_rn(w.x, 0.999f), -2.f), 2.f);
    o.y = fminf(fmaxf(__fmul_rn(w.y, 0.999f), -2.f), 2.f);
    o.z = fminf(fmaxf(__fmul_rn(w.z, 0.999f), -2.f), 2.f);
    o.w = fminf(fmaxf(__fmul_rn(w.w, 0.999f), -2.f), 2.f);
    o4[k] = o;
  }
  for (int off = 16; off; off >>= 1) acc += __shfl_down_sync(0xffffffffu, acc, off);
  __shared__ float sred[8];
  if ((threadIdx.x & 31) == 0) sred[threadIdx.x >> 5] = acc;
  __syncthreads();
  if (threadIdx.x == 0) {
    float a = 0.f;
    for (int w = 0; w < 8; w++) a += sred[w];
    // fused state update: noise -> sigmoid -> forced
    const unsigned B0 = 0u, B1 = 42u;
    unsigned n0, n1;
    keypair(B0, B1, 0u, n0, n1);
    const float LO = __int_as_float(0xBF7FFFFF);
    const float SQ2 = __int_as_float(0x3FB504F3);
    float f = f01(bits32(n0, n1, (unsigned)r));
    float u = fmaxf(LO, __fadd_rn(__fmul_rn(f, 2.0f), LO));
    float nrm = __fmul_rn(SQ2, erfinv_xla(u));
    float noise = __fmul_rn(0.05f, nrm);
    float x = __fadd_rn(a, noise);
    g_sState[r] = g_forced[r] ? 1.0f : (1.0f / (1.0f + expf(-x)));
  }
}

// ---------------- kGum: gumbels + {g,dv} + top-32 + wold prefetch ----------
__global__ void __launch_bounds__(1024) kGum(const float* __restrict__ W,
                                             const int* __restrict__ spark_pos) {
  extern __shared__ u64 sm_keys[];          // N keys = 64KB
  __shared__ u64 sm_red[32];
  __shared__ u64 sm_win;
  int i = blockIdx.x;
  int row = spark_pos[i];
  unsigned kc0 = g_kc0[i], kc1 = g_kc1[i];
  const float* wrow = W + (size_t)row * N;
  size_t base = (size_t)i * N;
  int tid = threadIdx.x;

  for (int j = tid; j < N; j += 1024) {
    unsigned b = bits32(kc0, kc1, (unsigned)j);
    float u = fmaxf(f01(b), 1.17549435e-38f);
    float g = -__nv_logf(-__nv_logf(u));
    float dv = divf(wrow[j]);
    float z0 = zf(g, dv, g_Mdec[j]);
    g_gd[base + j] = make_float2(g, dv);
    sm_keys[j] = packz(z0, j);
  }
  __syncthreads();

  u64 tmax = 0;
  #pragma unroll
  for (int t = 0; t < 8; t++) {
    u64 k = sm_keys[tid + t * 1024];
    if (k > tmax) tmax = k;
  }
  for (int rd = 0; rd < TOPT; rd++) {
    u64 v = tmax;
    for (int o = 16; o; o >>= 1) {
      u64 x = __shfl_down_sync(0xffffffffu, v, o);
      if (x > v) v = x;
    }
    if ((tid & 31) == 0) sm_red[tid >> 5] = v;
    __syncthreads();
    if (tid < 32) {
      u64 w = sm_red[tid];
      for (int o = 16; o; o >>= 1) {
        u64 x = __shfl_down_sync(0xffffffffu, w, o);
        if (x > w) w = x;
      }
      if (tid == 0) { sm_win = w; g_top[(size_t)i * TOPT + rd] = w; }
    }
    __syncthreads();
    u64 w = sm_win;
    if (tmax == w) {     // unique owner (keys unique)
      tmax = 0;
      #pragma unroll
      for (int t = 0; t < 8; t++) {
        int j = tid + t * 1024;
        u64 kk = sm_keys[j];
        if (kk == w) { sm_keys[j] = 0; kk = 0; }
        if (kk > tmax) tmax = kk;
      }
    }
  }
  // wold prefetch: W[cand, row] for the 32 candidates + randpos
  if (tid < TOPT) {
    u64 k = g_top[(size_t)i * TOPT + tid];
    int idx = (N - 1) - (int)(unsigned)(k & 0xffffffffu);
    g_wold[(size_t)i * 33 + tid] = W[(size_t)idx * N + row];
  } else if (tid == 32) {
    g_wold[(size_t)i * 33 + 32] = W[(size_t)g_randpos[i] * N + row];
  }
}

// ---------------- kScan: A||B pipelined serial scan, 1 barrier/iter --------
#define SMEM_SCAN (4 * N * 4 + K * TOPT * 8 + 2 * 16 * 8 + 2 * 16 * 4 + 512 * 4 + 10 * K * 4 + 2 * 12 * 4 + 128)

__global__ void __launch_bounds__(SCAN_T) kScan(const float* __restrict__ W,
                                                const int* __restrict__ sp,
                                                const float* __restrict__ se,
                                                const int* __restrict__ sa,
                                                float* __restrict__ out) {
  extern __shared__ __align__(16) unsigned char smraw[];
  float* s_sh = (float*)smraw;
  float* M_sh = s_sh + N;
  float* pnew = M_sh + N;
  int*   c_sh = (int*)(pnew + N);
  u64*   red = (u64*)(c_sh + N);      // [2][16]
  float* redw = (float*)(red + 32);   // [2][16]
  int*   dlist = (int*)(redw + 32);   // 512
  int*   sp_sh = dlist + 512;         // K
  int*   ex_sh = sp_sh + K;
  int*   rp_sh = ex_sh + K;
  float* edec_sh = (float*)(rp_sh + K);
  int*   reset_sh = (int*)(edec_sh + K);
  int*   res_pos = reset_sh + K;
  float* res_e = (float*)(res_pos + K);
  int*   res_age = (int*)(res_e + K);
  int*   stg = res_age + K;           // [2][12] stage: parity double buffer
  u64*   top_sh = (u64*)(((char*)(stg + 24)) + ((16 - (((size_t)(stg + 24)) & 15)) & 15));

  int tid = threadIdx.x;
  int lane = tid & 31;
  int wid = tid >> 5;
  const unsigned FULL = 0xffffffffu;

  for (int j = tid; j < N; j += SCAN_T) {
    s_sh[j] = g_sState[j];
    M_sh[j] = g_Mdec[j];
    c_sh[j] = 0;
    pnew[j] = 0.f;
  }
  for (int t = tid; t < K * TOPT; t += SCAN_T) top_sh[t] = g_top[t];
  if (tid < 32) { red[tid] = 0; redw[tid] = 0.f; }
  for (int i2 = tid; i2 < K; i2 += SCAN_T) {
    sp_sh[i2] = sp[i2];
    ex_sh[i2] = g_explore[i2];
    rp_sh[i2] = g_randpos[i2];
    float e = __fmul_rn(se[i2], 0.98f);
    int rs = (e < 0.05f) ? 1 : 0;
    edec_sh[i2] = e;
    reset_sh[i2] = rs;
    res_e[i2] = rs ? 1.0f : e;
    res_age[i2] = rs ? 0 : (sa[i2] + 1);
    res_pos[i2] = i2;                  // reset value (i % N == i for i<256)
  }
  __syncthreads();

  int nd = 0;
  // B-warp register double buffer of g_wold rows
  float woldC = 0.f, wrpC = 0.f, woldN = 0.f, wrpN = 0.f;
  if (wid == 0) {
    woldN = g_wold[lane];
    if (lane == 0) wrpN = g_wold[32];
  }

  for (int t = 0; t < K; t++) {
    // ---- commit stage from B_{t-1} (all threads, same-value writes) ----
    int fx0 = -1, fx1 = -1;
    if (t > 0) {
      int* sg = stg + ((t - 1) & 1) * 12;
      int sprev = sg[0], snxt = sg[1];
      pnew[sprev] = __int_as_float(sg[7]);
      c_sh[sprev] = sg[2];
      M_sh[snxt]  = __int_as_float(sg[8]);
      c_sh[snxt]  = sg[3];
      s_sh[snxt]  = __int_as_float(sg[9]);
      int a0 = sg[4], a1 = sg[5], ndn = sg[6];
      if (a0 >= 0) dlist[ndn - ((a1 >= 0) ? 2 : 1)] = a0;
      if (a1 >= 0) dlist[ndn - 1] = a1;
      nd = ndn;
      fx0 = sprev; fx1 = snxt;
    }

    if (wid > 0) {
      // ==== A: speculative dirty-scan for spark t+1 with paired wold ====
      if (t + 1 < K) {
        int atid = tid - 32;       // 0..511
        u64 pk = 0; float wd = 0.f;
        if (atid < nd) {
          int idx = dlist[atid];
          if (idx != sp_sh[t]) {
            int rn = sp_sh[t + 1];
            int c = c_sh[idx];
            float2 gd = g_gd[(size_t)(t + 1) * N + idx];
            wd = (rn < 256) ? g_Wc[(size_t)idx * 256 + rn]
                            : W[(size_t)idx * N + rn];
            float dv = ((c & 0xffff) == (rn + 1)) ? divf(pnew[idx]) : gd.y;
            pk = packz(zf(gd.x, dv, M_sh[idx]), idx);
          }
        }
        for (int o = 16; o; o >>= 1) {
          u64 v = __shfl_down_sync(FULL, pk, o);
          float w2 = __shfl_down_sync(FULL, wd, o);
          if (v > pk) { pk = v; wd = w2; }
        }
        if (lane == 0) {
          red[((t + 1) & 1) * 16 + (wid - 1)] = pk;
          redw[((t + 1) & 1) * 16 + (wid - 1)] = wd;
        }
      }
    } else {
      // ==== B: decision for spark t ====
      int r = sp_sh[t];
      int rp = rp_sh[t];
      // rotate wold register buffers + prefetch next row
      woldC = woldN; wrpC = wrpN;
      if (t + 1 < K) {
        woldN = g_wold[(size_t)(t + 1) * 33 + lane];
        if (lane == 0) wrpN = g_wold[(size_t)(t + 1) * 33 + 32];
      }
      u64 cnd = top_sh[t * TOPT + lane];   // sorted desc
      int cidx = (N - 1) - (int)(unsigned)(cnd & 0xffffffffu);

      // fixup: recompute exactly at B_{t-1}'s two positions (post-commit)
      u64 fmax = 0; float fwold = 0.f;
      int fx = (lane == 0) ? fx0 : ((lane == 1) ? fx1 : -1);
      if (fx >= 0) {
        fwold = (r < 256) ? g_Wc[(size_t)fx * 256 + r]
                          : W[(size_t)fx * N + r];
        int c = c_sh[fx];
        float2 gd = g_gd[(size_t)t * N + fx];
        float dv = ((c & 0xffff) == (r + 1)) ? divf(pnew[fx]) : gd.y;
        fmax = packz(zf(gd.x, dv, M_sh[fx]), fx);
      }
      u64 dmax = (lane < 16) ? red[(t & 1) * 16 + lane] : 0;
      float dwold = (lane < 16) ? redw[(t & 1) * 16 + lane] : 0.f;
      if (fmax > dmax) { dmax = fmax; dwold = fwold; }
      for (int o = 16; o; o >>= 1) {
        u64 v = __shfl_xor_sync(FULL, dmax, o);
        float w2 = __shfl_xor_sync(FULL, dwold, o);
        if (v > dmax) { dmax = v; dwold = w2; }
      }

      bool clean = !(c_sh[cidx] & BIT_LST);
      unsigned mk = __ballot_sync(FULL, clean);
      int Lwin = mk ? (__ffs(mk) - 1) : 0;
      u64 best;
      bool cleanWin = false;
      bool fbWin = false;
      if (mk) {
        u64 bc = __shfl_sync(FULL, cnd, Lwin);
        if (dmax > bc) { best = dmax; } else { best = bc; cleanWin = true; }
      } else {
        u64 last = __shfl_sync(FULL, cnd, TOPT - 1);
        if (dmax > last) {
          best = dmax;                     // clean max <= last < dmax
        } else {
          // exact full-row fallback on current (post-B_{t-1}) state
          u64 fb = 0;
          for (int j = lane; j < N; j += 32) {
            int c = c_sh[j];
            float2 gd = g_gd[(size_t)t * N + j];
            float dv = ((c & 0xffff) == (r + 1)) ? divf(pnew[j]) : gd.y;
            u64 p2 = packz(zf(gd.x, dv, M_sh[j]), j);
            if (p2 > fb) fb = p2;
          }
          for (int o = 16; o; o >>= 1) {
            u64 v = __shfl_xor_sync(FULL, fb, o);
            if (v > fb) fb = v;
          }
          best = fb;
          fbWin = true;
        }
      }
      float wcL = __shfl_sync(FULL, woldC, Lwin);

      if (lane == 0) {
        int cat = (N - 1) - (int)(unsigned)(best & 0xffffffffu);
        int ex = ex_sh[t];
        int nxt = ex ? rp : cat;
        int prev = r;
        int cp = c_sh[prev];
        float wold;
        if ((cp & 0xffff) == (nxt + 1)) {
          wold = pnew[prev];
        } else if (ex) {
          wold = wrpC;
        } else if (fbWin) {
          wold = (prev < 256) ? g_Wc[(size_t)nxt * 256 + prev]
                              : W[(size_t)nxt * N + prev];
        } else if (cleanWin) {
          wold = wcL;
        } else {
          wold = dwold;                    // dirty winner's paired wold
        }
        float pv = __fadd_rn(__fmul_rn(wold, 0.95f),
                             __fmul_rn(s_sh[prev], 0.05f));
        int ndn = nd;
        int a0 = -1, a1 = -1;
        int ncp = (cp & ~0xffff) | (nxt + 1);
        if (!(cp & BIT_LST)) { a0 = prev; ndn++; ncp |= BIT_LST; }
        int cn = (nxt == prev) ? ncp : c_sh[nxt];
        float Mv = __fadd_rn(M_sh[nxt], 0.2f);
        int ncn = cn | BIT_DEP;
        if (!(cn & BIT_LST)) { a1 = nxt; ndn++; ncn |= BIT_LST; }
        // stage the updates (committed by all threads next slot)
        int* sg = stg + (t & 1) * 12;
        sg[0] = prev; sg[1] = nxt; sg[2] = ncp; sg[3] = ncn;
        sg[4] = a0; sg[5] = a1; sg[6] = ndn;
        sg[7] = __float_as_int(pv);
        sg[8] = __float_as_int(Mv);
        sg[9] = __float_as_int(edec_sh[t]);
        if (!reset_sh[t]) res_pos[t] = nxt;
      }
    }
    __syncthreads();
  }

  // final commit of B_{K-1} (all threads, same values; dlist not needed)
  {
    int* sg = stg + ((K - 1) & 1) * 12;
    int sprev = sg[0], snxt = sg[1];
    pnew[sprev] = __int_as_float(sg[7]);
    c_sh[sprev] = sg[2];
    M_sh[snxt]  = __int_as_float(sg[8]);
    c_sh[snxt]  = sg[3];
    s_sh[snxt]  = __int_as_float(sg[9]);
  }
  __syncthreads();

  // epilogue: outputs (layout: pos[K], W[N*N], s[N], M[N], energy[K], age[K])
  const size_t OUT_W = K;
  const size_t OUT_S = OUT_W + (size_t)N * N;
  const size_t OUT_M = OUT_S + N;
  const size_t OUT_E = OUT_M + N;
  const size_t OUT_A = OUT_E + K;
  for (int j = tid; j < N; j += SCAN_T) {
    out[OUT_S + j] = s_sh[j];
    out[OUT_M + j] = M_sh[j];
    int c = c_sh[j];
    int prow = c & 0xffff;
    if (prow) {
      size_t idx = (size_t)(prow - 1) * N + (size_t)j;
      out[OUT_W + idx] = fminf(fmaxf(__fmul_rn(pnew[j], 0.999f), -2.f), 2.f);
    }
  }
  for (int i2 = tid; i2 < K; i2 += SCAN_T) {
    out[i2] = (float)res_pos[i2];
    out[OUT_E + i2] = res_e[i2];
    out[OUT_A + i2] = (float)res_age[i2];
  }
}

// ---------------- launch ----------------
extern "C" void kernel_launch(void* const* d_in, const int* in_sizes, int n_in,
                              void* d_out, int out_size) {
  const float* W = (const float*)d_in[0];
  const float* s = (const float*)d_in[1];
  const float* M = (const float*)d_in[2];
  const int* sp = (const int*)d_in[3];
  const float* se = (const float*)d_in[4];
  const int* sa = (const int*)d_in[5];
  float* out = (float*)d_out;

  cudaFuncSetAttribute(kGum, cudaFuncAttributeMaxDynamicSharedMemorySize,
                       N * 8);
  cudaFuncSetAttribute(kScan, cudaFuncAttributeMaxDynamicSharedMemorySize,
                       SMEM_SCAN);

  kInit<<<1, 256>>>(M, sp, sa);
  kMV<<<N, 256>>>(W, s, out + K);      // out_W starts right after pos[K]
  kGum<<<K, 1024, N * 8>>>(W, sp);
  kScan<<<1, SCAN_T, SMEM_SCAN>>>(W, sp, se, sa, out);
}

// round 16
// speedup vs baseline: 1.2228x; 1.1416x over previous
#include <cuda_runtime.h>
#include <stdint.h>
#include <stddef.h>

// SparkFieldNet single step, bit-matching JAX threefry-2x32 RNG
// (jax_threefry_partitionable scheme).
// Inputs: 0=W[N*N] f32, 1=s[N] f32, 2=M[N] f32, 3=spark_pos[K] i32,
//         4=spark_energy[K] f32, 5=spark_age[K] i32
// Output: concat(pos[K], W[N*N], s[N], M[N], energy[K], age[K]) as float32.

#define N 8192
#define K 256
#define TOPT 32
#define BIT_DEP (1 << 16)
#define BIT_LST (1 << 17)
#define SCAN_T 512

extern "C" __device__ float __nv_logf(float);

typedef unsigned long long u64;

// ---- device scratch ----
__device__ float2 g_gd[(size_t)K * N];    // {gumbel, div} per spark x pos (16MB)
__device__ float  g_Wc[(size_t)N * 256];  // W[:, 0:256] compact copy (8MB)
__device__ u64    g_top[(size_t)K * TOPT];
__device__ float  g_wold[(size_t)K * 33]; // W[cand, sp_i] for top32 + randpos
__device__ float  g_sState[N];
__device__ float  g_Mdec[N];
__device__ int    g_forced[N];
__device__ unsigned g_kc0[K], g_kc1[K];
__device__ int    g_explore[K];
__device__ int    g_randpos[K];

// ---------------- Threefry-2x32 (JAX-exact, 20 rounds) ----------------
__device__ __forceinline__ void tf2x32(unsigned k0, unsigned k1,
                                       unsigned x0, unsigned x1,
                                       unsigned& o0, unsigned& o1) {
  unsigned ks2 = k0 ^ k1 ^ 0x1BD11BDAu;
  x0 += k0; x1 += k1;
#define TFR(r) { x0 += x1; x1 = (x1 << (r)) | (x1 >> (32 - (r))); x1 ^= x0; }
  TFR(13) TFR(15) TFR(26) TFR(6)   x0 += k1;  x1 += ks2 + 1u;
  TFR(17) TFR(29) TFR(16) TFR(24)  x0 += ks2; x1 += k0 + 2u;
  TFR(13) TFR(15) TFR(26) TFR(6)   x0 += k0;  x1 += k1 + 3u;
  TFR(17) TFR(29) TFR(16) TFR(24)  x0 += k1;  x1 += ks2 + 4u;
  TFR(13) TFR(15) TFR(26) TFR(6)   x0 += ks2; x1 += k0 + 5u;
#undef TFR
  o0 = x0; o1 = x1;
}

__device__ __forceinline__ void keypair(unsigned k0, unsigned k1, unsigned i,
                                        unsigned& o0, unsigned& o1) {
  tf2x32(k0, k1, 0u, i, o0, o1);
}

__device__ __forceinline__ unsigned bits32(unsigned k0, unsigned k1, unsigned j) {
  unsigned o0, o1;
  tf2x32(k0, k1, 0u, j, o0, o1);
  return o0 ^ o1;
}

__device__ __forceinline__ float f01(unsigned b) {
  return __fadd_rn(__uint_as_float((b >> 9) | 0x3f800000u), -1.0f);
}

__device__ __forceinline__ u64 packz(float z, int j) {
  unsigned zu = __float_as_uint(z);
  zu = (zu & 0x80000000u) ? ~zu : (zu | 0x80000000u);
  return ((u64)zu << 32) | (unsigned)(N - 1 - j);   // tie -> smaller index wins
}

__device__ __forceinline__ float divf(float w) {
  return __fdiv_rn(__fadd_rn(fmaxf(w, 0.0f), 1e-6f), 0.3f);
}

__device__ __forceinline__ float zf(float g, float dv, float m) {
  return __fadd_rn(g, __fadd_rn(dv, __fmul_rn(0.8f, m)));
}

// discard-loads to warm L1 (not eliminable by the compiler)
__device__ __forceinline__ void warm64(const void* p) {
  u64 d;
  asm volatile("ld.global.nc.b64 %0, [%1];" : "=l"(d) : "l"(p));
}
__device__ __forceinline__ void warm32(const void* p) {
  unsigned d;
  asm volatile("ld.global.nc.b32 %0, [%1];" : "=r"(d) : "l"(p));
}

// XLA ErfInv f32 polynomial (Giles)
__device__ __forceinline__ float erfinv_xla(float x) {
  float w = -log1pf(-__fmul_rn(x, x));
  float p;
  if (w < 5.0f) {
    w = w - 2.5f;
    p = 2.81022636e-08f;
    p = fmaf(p, w, 3.43273939e-07f);
    p = fmaf(p, w, -3.5233877e-06f);
    p = fmaf(p, w, -4.39150654e-06f);
    p = fmaf(p, w, 0.00021858087f);
    p = fmaf(p, w, -0.00125372503f);
    p = fmaf(p, w, -0.00417768164f);
    p = fmaf(p, w, 0.246640727f);
    p = fmaf(p, w, 1.50140941f);
  } else {
    w = sqrtf(w) - 3.0f;
    p = -0.000200214257f;
    p = fmaf(p, w, 0.000100950558f);
    p = fmaf(p, w, 0.00134934322f);
    p = fmaf(p, w, -0.00367342844f);
    p = fmaf(p, w, 0.00573950773f);
    p = fmaf(p, w, -0.0076224613f);
    p = fmaf(p, w, 0.00943887047f);
    p = fmaf(p, w, 1.00167406f);
    p = fmaf(p, w, 2.83297682f);
  }
  return p * x;
}

// ---------------- kInit: forced mask, M decay, per-spark keys --------------
__global__ void __launch_bounds__(256) kInit(const float* __restrict__ M_in,
                                             const int* __restrict__ spark_pos,
                                             const int* __restrict__ spark_age) {
  int t = threadIdx.x;
  for (int j = t; j < N; j += 256) {
    g_forced[j] = 0;
    g_Mdec[j] = __fmul_rn(M_in[j], 0.95f);
  }
  __syncthreads();

  const unsigned B0 = 0u, B1 = 42u;
  unsigned kexp0, kexp1, krand0, krand1, kcat0, kcat1;
  keypair(B0, B1, 1u, kexp0, kexp1);
  keypair(B0, B1, 2u, krand0, krand1);
  keypair(B0, B1, 3u, kcat0, kcat1);

  int i = t;
  unsigned ke0, ke1;
  keypair(kexp0, kexp1, (unsigned)i, ke0, ke1);
  g_explore[i] = (f01(bits32(ke0, ke1, 0u)) < 0.05f) ? 1 : 0;
  unsigned kr0, kr1, k20, k21;
  keypair(krand0, krand1, (unsigned)i, kr0, kr1);
  keypair(kr0, kr1, 1u, k20, k21);
  g_randpos[i] = (int)(bits32(k20, k21, 0u) & (unsigned)(N - 1));
  unsigned kc0, kc1;
  keypair(kcat0, kcat1, (unsigned)i, kc0, kc1);
  g_kc0[i] = kc0;
  g_kc1[i] = kc1;
  if (spark_age[i] < 5) g_forced[spark_pos[i]] = 1;
}

// ---------------- kMV: matvec + W decay/clip + Wc copy + state -------------
__global__ void __launch_bounds__(256) kMV(const float* __restrict__ W,
                                           const float* __restrict__ s_in,
                                           float* __restrict__ outW) {
  int r = blockIdx.x;
  const float4* w4 = (const float4*)(W + (size_t)r * N);
  const float4* s4 = (const float4*)s_in;
  float4* o4 = (float4*)(outW + (size_t)r * N);
  float4* wc4 = (float4*)(g_Wc + (size_t)r * 256);
  float acc = 0.f;
  for (int k = threadIdx.x; k < N / 4; k += 256) {
    float4 w = w4[k];
    float4 sv = s4[k];
    acc += w.x * (sv.x * 0.95f) + w.y * (sv.y * 0.95f)
         + w.z * (sv.z * 0.95f) + w.w * (sv.w * 0.95f);
    if (k < 64) wc4[k] = w;                 // original W[:,0:256] slice
    float4 o;
    o.x = fminf(fmaxf(__fmul_rn(w.x, 0.999f), -2.f), 2.f);
    o.y = fminf(fmaxf(__fmul_rn(w.y, 0.999f), -2.f), 2.f);
    o.z = fminf(fmaxf(__fmul_rn(w.z, 0.999f), -2.f), 2.f);
    o.w = fminf(fmaxf(__fmul_rn(w.w, 0.999f), -2.f), 2.f);
    o4[k] = o;
  }
  for (int off = 16; off; off >>= 1) acc += __shfl_down_sync(0xffffffffu, acc, off);
  __shared__ float sred[8];
  if ((threadIdx.x & 31) == 0) sred[threadIdx.x >> 5] = acc;
  __syncthreads();
  if (threadIdx.x == 0) {
    float a = 0.f;
    for (int w = 0; w < 8; w++) a += sred[w];
    // fused state update: noise -> sigmoid -> forced
    const unsigned B0 = 0u, B1 = 42u;
    unsigned n0, n1;
    keypair(B0, B1, 0u, n0, n1);
    const float LO = __int_as_float(0xBF7FFFFF);
    const float SQ2 = __int_as_float(0x3FB504F3);
    float f = f01(bits32(n0, n1, (unsigned)r));
    float u = fmaxf(LO, __fadd_rn(__fmul_rn(f, 2.0f), LO));
    float nrm = __fmul_rn(SQ2, erfinv_xla(u));
    float noise = __fmul_rn(0.05f, nrm);
    float x = __fadd_rn(a, noise);
    g_sState[r] = g_forced[r] ? 1.0f : (1.0f / (1.0f + expf(-x)));
  }
}

// ---------------- kGum: gumbels + {g,dv} + top-32 + wold prefetch ----------
__global__ void __launch_bounds__(1024) kGum(const float* __restrict__ W,
                                             const int* __restrict__ spark_pos) {
  extern __shared__ u64 sm_keys[];          // N keys = 64KB
  __shared__ u64 sm_red[32];
  __shared__ u64 sm_win;
  int i = blockIdx.x;
  int row = spark_pos[i];
  unsigned kc0 = g_kc0[i], kc1 = g_kc1[i];
  const float* wrow = W + (size_t)row * N;
  size_t base = (size_t)i * N;
  int tid = threadIdx.x;

  for (int j = tid; j < N; j += 1024) {
    unsigned b = bits32(kc0, kc1, (unsigned)j);
    float u = fmaxf(f01(b), 1.17549435e-38f);
    float g = -__nv_logf(-__nv_logf(u));
    float dv = divf(wrow[j]);
    float z0 = zf(g, dv, g_Mdec[j]);
    g_gd[base + j] = make_float2(g, dv);
    sm_keys[j] = packz(z0, j);
  }
  __syncthreads();

  u64 tmax = 0;
  #pragma unroll
  for (int t = 0; t < 8; t++) {
    u64 k = sm_keys[tid + t * 1024];
    if (k > tmax) tmax = k;
  }
  for (int rd = 0; rd < TOPT; rd++) {
    u64 v = tmax;
    for (int o = 16; o; o >>= 1) {
      u64 x = __shfl_down_sync(0xffffffffu, v, o);
      if (x > v) v = x;
    }
    if ((tid & 31) == 0) sm_red[tid >> 5] = v;
    __syncthreads();
    if (tid < 32) {
      u64 w = sm_red[tid];
      for (int o = 16; o; o >>= 1) {
        u64 x = __shfl_down_sync(0xffffffffu, w, o);
        if (x > w) w = x;
      }
      if (tid == 0) { sm_win = w; g_top[(size_t)i * TOPT + rd] = w; }
    }
    __syncthreads();
    u64 w = sm_win;
    if (tmax == w) {     // unique owner (keys unique)
      tmax = 0;
      #pragma unroll
      for (int t = 0; t < 8; t++) {
        int j = tid + t * 1024;
        u64 kk = sm_keys[j];
        if (kk == w) { sm_keys[j] = 0; kk = 0; }
        if (kk > tmax) tmax = kk;
      }
    }
  }
  // wold prefetch: W[cand, row] for the 32 candidates + randpos
  if (tid < TOPT) {
    u64 k = g_top[(size_t)i * TOPT + tid];
    int idx = (N - 1) - (int)(unsigned)(k & 0xffffffffu);
    g_wold[(size_t)i * 33 + tid] = W[(size_t)idx * N + row];
  } else if (tid == 32) {
    g_wold[(size_t)i * 33 + 32] = W[(size_t)g_randpos[i] * N + row];
  }
}

// ---------------- kScan: R10 skeleton, B purged of L2 loads ----------------
// smem: s[N] M[N] pnew[N] c[N] (128KB) + top[K*32] (64KB) + small
#define SMEM_SCAN (4 * N * 4 + K * TOPT * 8 + 16 * 8 + 16 * 4 + 512 * 4 + 8 * K * 4 + 128)

__global__ void __launch_bounds__(SCAN_T) kScan(const float* __restrict__ W,
                                                const int* __restrict__ sp,
                                                const float* __restrict__ se,
                                                const int* __restrict__ sa,
                                                float* __restrict__ out) {
  extern __shared__ __align__(16) unsigned char smraw[];
  float* s_sh = (float*)smraw;
  float* M_sh = s_sh + N;
  float* pnew = M_sh + N;
  int*   c_sh = (int*)(pnew + N);
  u64*   top_sh = (u64*)(c_sh + N);   // K*TOPT
  u64*   red = top_sh + K * TOPT;     // 16
  float* redw = (float*)(red + 16);   // 16
  int*   dlist = (int*)(redw + 16);   // 512
  int*   sp_sh = dlist + 512;         // K
  int*   ex_sh = sp_sh + K;
  int*   rp_sh = ex_sh + K;
  float* edec_sh = (float*)(rp_sh + K);
  int*   reset_sh = (int*)(edec_sh + K);
  int*   res_pos = reset_sh + K;
  float* res_e = (float*)(res_pos + K);
  int*   res_age = (int*)(res_e + K);
  __shared__ int nd_sh;

  int tid = threadIdx.x;
  const unsigned FULL = 0xffffffffu;
  for (int j = tid; j < N; j += SCAN_T) {
    s_sh[j] = g_sState[j];
    M_sh[j] = g_Mdec[j];
    c_sh[j] = 0;
    pnew[j] = 0.f;
  }
  for (int t = tid; t < K * TOPT; t += SCAN_T) top_sh[t] = g_top[t];
  if (tid < K) {
    sp_sh[tid] = sp[tid];
    ex_sh[tid] = g_explore[tid];
    rp_sh[tid] = g_randpos[tid];
    float e = __fmul_rn(se[tid], 0.98f);
    int rs = (e < 0.05f) ? 1 : 0;
    edec_sh[tid] = e;
    reset_sh[tid] = rs;
    res_e[tid] = rs ? 1.0f : e;
    res_age[tid] = rs ? 0 : (sa[tid] + 1);
    res_pos[tid] = tid;                // reset value (i % N == i for i<256)
  }
  if (tid == 0) nd_sh = 0;
  __syncthreads();

  int nd = 0;        // dirty count valid at iteration start
  int ndpref = 0;    // slots with registers prefetched for this iteration
  float2 pre = make_float2(0.f, 0.f);
  float wdPre = 0.f;
  // B-warp register double buffer of g_wold rows
  float woldC = 0.f, wrpC = 0.f, woldN = 0.f, wrpN = 0.f;
  if (tid < 32) {
    woldN = g_wold[tid];
    if (tid == 0) wrpN = g_wold[32];
  }

  for (int i = 0; i < K; i++) {
    int r = sp_sh[i];
    size_t base = (size_t)i * N;

    // ---- phase A: dirty recompute + paired wold (one slot per thread) ----
    u64 pk = 0; float wd = 0.f;
    if (tid < nd) {
      int idx = dlist[tid];
      float2 gd; float w0;
      if (tid < ndpref) { gd = pre; w0 = wdPre; }
      else {
        gd = g_gd[base + idx];                        // L1-warmed
        w0 = (r < 256) ? g_Wc[(size_t)idx * 256 + r]
                       : W[(size_t)idx * N + r];
      }
      int c = c_sh[idx];
      float dv = ((c & 0xffff) == (r + 1)) ? divf(pnew[idx]) : gd.y;
      pk = packz(zf(gd.x, dv, M_sh[idx]), idx);
      wd = w0;
    }
    for (int o = 16; o; o >>= 1) {
      u64 v = __shfl_down_sync(FULL, pk, o);
      float w2 = __shfl_down_sync(FULL, wd, o);
      if (v > pk) { pk = v; wd = w2; }
    }
    if ((tid & 31) == 0) { red[tid >> 5] = pk; redw[tid >> 5] = wd; }
    // prefetch registers for next iteration's existing dirty slots
    if (i + 1 < K && tid < nd) {
      int idx = dlist[tid];
      pre = g_gd[base + N + idx];
      int rn = sp_sh[i + 1];
      wdPre = (rn < 256) ? g_Wc[(size_t)idx * 256 + rn]
                         : W[(size_t)idx * N + rn];
    }
    int ndpref_next = nd;
    __syncthreads();

    // ---- phase B: warp 0 picks winner, lane 0 applies the update ----
    if (tid < 32) {
      int lane = tid;
      int prev = r;
      int rp = rp_sh[i];
      // rotate wold register buffers + prefetch next row
      woldC = woldN; wrpC = wrpN;
      if (i + 1 < K) {
        woldN = g_wold[(size_t)(i + 1) * 33 + lane];
        if (lane == 0) wrpN = g_wold[(size_t)(i + 1) * 33 + 32];
      }
      // lane-0 early prefetch of serial-section operands
      int cpPre = 0; float pnPre = 0.f, spPre = 0.f;
      if (lane == 0) { cpPre = c_sh[prev]; pnPre = pnew[prev]; spPre = s_sh[prev]; }

      u64 cnd = top_sh[i * TOPT + lane];   // sorted desc
      int cidx = (N - 1) - (int)(unsigned)(cnd & 0xffffffffu);
      // warm next-iter lines for potential new dirty slots
      if (i + 1 < K) {
        int rn = sp_sh[i + 1];
        warm64(&g_gd[base + N + cidx]);
        if (rn < 256) warm32(&g_Wc[(size_t)cidx * 256 + rn]);
        if (lane == 0) {
          warm64(&g_gd[base + N + prev]);
          if (rn < 256) warm32(&g_Wc[(size_t)prev * 256 + rn]);
        }
        if (lane == 1) {
          warm64(&g_gd[base + N + rp]);
          if (rn < 256) warm32(&g_Wc[(size_t)rp * 256 + rn]);
        }
      }

      u64 dmax = (lane < 16) ? red[lane] : 0;
      float dwold = (lane < 16) ? redw[lane] : 0.f;
      for (int o = 16; o; o >>= 1) {
        u64 v = __shfl_xor_sync(FULL, dmax, o);
        float w2 = __shfl_xor_sync(FULL, dwold, o);
        if (v > dmax) { dmax = v; dwold = w2; }
      }

      bool clean = !(c_sh[cidx] & BIT_LST);
      unsigned mk = __ballot_sync(FULL, clean);
      int Lwin = mk ? (__ffs(mk) - 1) : 0;
      u64 best;
      bool cleanWin = false;
      bool fbWin = false;
      if (mk) {
        u64 bc = __shfl_sync(FULL, cnd, Lwin);
        if (dmax > bc) { best = dmax; } else { best = bc; cleanWin = true; }
      } else {
        u64 last = __shfl_sync(FULL, cnd, TOPT - 1);
        if (dmax > last) {
          best = dmax;                     // clean max <= last < dmax
        } else {
          // exact full-row fallback (not expected to trigger)
          u64 fb = 0;
          for (int j = lane; j < N; j += 32) {
            int c = c_sh[j];
            float2 gd = g_gd[base + j];
            float dv = ((c & 0xffff) == (r + 1)) ? divf(pnew[j]) : gd.y;
            u64 p2 = packz(zf(gd.x, dv, M_sh[j]), j);
            if (p2 > fb) fb = p2;
          }
          for (int o = 16; o; o >>= 1) {
            u64 v = __shfl_xor_sync(FULL, fb, o);
            if (v > fb) fb = v;
          }
          best = fb;
          fbWin = true;
        }
      }
      float wcL = __shfl_sync(FULL, woldC, Lwin);

      if (lane == 0) {
        int cat = (N - 1) - (int)(unsigned)(best & 0xffffffffu);
        int ex = ex_sh[i];
        int nxt = ex ? rp : cat;
        int cp = cpPre;
        float wold;
        if ((cp & 0xffff) == (nxt + 1)) {
          wold = pnPre;
        } else if (ex) {
          wold = wrpC;
        } else if (fbWin) {
          wold = (prev < 256) ? g_Wc[(size_t)nxt * 256 + prev]
                              : W[(size_t)nxt * N + prev];
        } else if (cleanWin) {
          wold = wcL;
        } else {
          wold = dwold;                    // dirty winner's paired wold
        }
        pnew[prev] = __fadd_rn(__fmul_rn(wold, 0.95f),
                               __fmul_rn(spPre, 0.05f));
        int ndl = nd;
        int ncp = (cp & ~0xffff) | (nxt + 1);
        if (!(cp & BIT_LST)) { dlist[ndl] = prev; ndl++; ncp |= BIT_LST; }
        c_sh[prev] = ncp;
        int cn = (nxt == prev) ? ncp : c_sh[nxt];
        M_sh[nxt] = __fadd_rn(M_sh[nxt], 0.2f);
        int ncn = cn | BIT_DEP;
        if (!(cn & BIT_LST)) { dlist[ndl] = nxt; ndl++; ncn |= BIT_LST; }
        c_sh[nxt] = ncn;
        s_sh[nxt] = edec_sh[i];
        if (!reset_sh[i]) res_pos[i] = nxt;
        nd_sh = ndl;
      }
    }
    __syncthreads();
    nd = nd_sh;
    ndpref = ndpref_next;
  }

  // epilogue: outputs (layout: pos[K], W[N*N], s[N], M[N], energy[K], age[K])
  const size_t OUT_W = K;
  const size_t OUT_S = OUT_W + (size_t)N * N;
  const size_t OUT_M = OUT_S + N;
  const size_t OUT_E = OUT_M + N;
  const size_t OUT_A = OUT_E + K;
  for (int j = tid; j < N; j += SCAN_T) {
    out[OUT_S + j] = s_sh[j];
    out[OUT_M + j] = M_sh[j];
    int c = c_sh[j];
    int prow = c & 0xffff;
    if (prow) {
      size_t idx = (size_t)(prow - 1) * N + (size_t)j;
      out[OUT_W + idx] = fminf(fmaxf(__fmul_rn(pnew[j], 0.999f), -2.f), 2.f);
    }
  }
  for (int i2 = tid; i2 < K; i2 += SCAN_T) {
    out[i2] = (float)res_pos[i2];
    out[OUT_E + i2] = res_e[i2];
    out[OUT_A + i2] = (float)res_age[i2];
  }
}

// ---------------- launch ----------------
extern "C" void kernel_launch(void* const* d_in, const int* in_sizes, int n_in,
                              void* d_out, int out_size) {
  const float* W = (const float*)d_in[0];
  const float* s = (const float*)d_in[1];
  const float* M = (const float*)d_in[2];
  const int* sp = (const int*)d_in[3];
  const float* se = (const float*)d_in[4];
  const int* sa = (const int*)d_in[5];
  float* out = (float*)d_out;

  cudaFuncSetAttribute(kGum, cudaFuncAttributeMaxDynamicSharedMemorySize,
                       N * 8);
  cudaFuncSetAttribute(kScan, cudaFuncAttributeMaxDynamicSharedMemorySize,
                       SMEM_SCAN);

  kInit<<<1, 256>>>(M, sp, sa);
  kMV<<<N, 256>>>(W, s, out + K);      // out_W starts right after pos[K]
  kGum<<<K, 1024, N * 8>>>(W, sp);
  kScan<<<1, SCAN_T, SMEM_SCAN>>>(W, sp, se, sa, out);
}

// round 17
// speedup vs baseline: 1.3382x; 1.0944x over previous
#include <cuda_runtime.h>
#include <stdint.h>
#include <stddef.h>

// SparkFieldNet single step, bit-matching JAX threefry-2x32 RNG
// (jax_threefry_partitionable scheme).
// Inputs: 0=W[N*N] f32, 1=s[N] f32, 2=M[N] f32, 3=spark_pos[K] i32,
//         4=spark_energy[K] f32, 5=spark_age[K] i32
// Output: concat(pos[K], W[N*N], s[N], M[N], energy[K], age[K]) as float32.

#define N 8192
#define K 256
#define TOPT 32
#define BIT_DEP (1 << 16)
#define BIT_LST (1 << 17)
#define SCAN_T 544   /* warp0 = decision, warps 1..16 = 512 dirty-scan threads */

extern "C" __device__ float __nv_logf(float);

typedef unsigned long long u64;

// ---- device scratch ----
__device__ float2 g_gd[(size_t)K * N];    // {gumbel, div} per spark x pos (16MB)
__device__ float  g_Wc[(size_t)N * 256];  // W[:, 0:256] compact copy (8MB)
__device__ u64    g_top[(size_t)K * TOPT];
__device__ float  g_wold[(size_t)K * 33]; // W[cand, sp_i] for top32 + randpos
__device__ float  g_sState[N];
__device__ float  g_Mdec[N];
__device__ int    g_forced[N];
__device__ unsigned g_kc0[K], g_kc1[K];
__device__ int    g_explore[K];
__device__ int    g_randpos[K];

// ---------------- Threefry-2x32 (JAX-exact, 20 rounds) ----------------
__device__ __forceinline__ void tf2x32(unsigned k0, unsigned k1,
                                       unsigned x0, unsigned x1,
                                       unsigned& o0, unsigned& o1) {
  unsigned ks2 = k0 ^ k1 ^ 0x1BD11BDAu;
  x0 += k0; x1 += k1;
#define TFR(r) { x0 += x1; x1 = (x1 << (r)) | (x1 >> (32 - (r))); x1 ^= x0; }
  TFR(13) TFR(15) TFR(26) TFR(6)   x0 += k1;  x1 += ks2 + 1u;
  TFR(17) TFR(29) TFR(16) TFR(24)  x0 += ks2; x1 += k0 + 2u;
  TFR(13) TFR(15) TFR(26) TFR(6)   x0 += k0;  x1 += k1 + 3u;
  TFR(17) TFR(29) TFR(16) TFR(24)  x0 += k1;  x1 += ks2 + 4u;
  TFR(13) TFR(15) TFR(26) TFR(6)   x0 += ks2; x1 += k0 + 5u;
#undef TFR
  o0 = x0; o1 = x1;
}

__device__ __forceinline__ void keypair(unsigned k0, unsigned k1, unsigned i,
                                        unsigned& o0, unsigned& o1) {
  tf2x32(k0, k1, 0u, i, o0, o1);
}

__device__ __forceinline__ unsigned bits32(unsigned k0, unsigned k1, unsigned j) {
  unsigned o0, o1;
  tf2x32(k0, k1, 0u, j, o0, o1);
  return o0 ^ o1;
}

__device__ __forceinline__ float f01(unsigned b) {
  return __fadd_rn(__uint_as_float((b >> 9) | 0x3f800000u), -1.0f);
}

__device__ __forceinline__ u64 packz(float z, int j) {
  unsigned zu = __float_as_uint(z);
  zu = (zu & 0x80000000u) ? ~zu : (zu | 0x80000000u);
  return ((u64)zu << 32) | (unsigned)(N - 1 - j);   // tie -> smaller index wins
}

__device__ __forceinline__ float divf(float w) {
  return __fdiv_rn(__fadd_rn(fmaxf(w, 0.0f), 1e-6f), 0.3f);
}

__device__ __forceinline__ float zf(float g, float dv, float m) {
  return __fadd_rn(g, __fadd_rn(dv, __fmul_rn(0.8f, m)));
}

// discard-loads to warm L1 (not eliminable by the compiler)
__device__ __forceinline__ void warm64(const void* p) {
  u64 d;
  asm volatile("ld.global.nc.b64 %0, [%1];" : "=l"(d) : "l"(p));
}
__device__ __forceinline__ void warm32(const void* p) {
  unsigned d;
  asm volatile("ld.global.nc.b32 %0, [%1];" : "=r"(d) : "l"(p));
}

// XLA ErfInv f32 polynomial (Giles)
__device__ __forceinline__ float erfinv_xla(float x) {
  float w = -log1pf(-__fmul_rn(x, x));
  float p;
  if (w < 5.0f) {
    w = w - 2.5f;
    p = 2.81022636e-08f;
    p = fmaf(p, w, 3.43273939e-07f);
    p = fmaf(p, w, -3.5233877e-06f);
    p = fmaf(p, w, -4.39150654e-06f);
    p = fmaf(p, w, 0.00021858087f);
    p = fmaf(p, w, -0.00125372503f);
    p = fmaf(p, w, -0.00417768164f);
    p = fmaf(p, w, 0.246640727f);
    p = fmaf(p, w, 1.50140941f);
  } else {
    w = sqrtf(w) - 3.0f;
    p = -0.000200214257f;
    p = fmaf(p, w, 0.000100950558f);
    p = fmaf(p, w, 0.00134934322f);
    p = fmaf(p, w, -0.00367342844f);
    p = fmaf(p, w, 0.00573950773f);
    p = fmaf(p, w, -0.0076224613f);
    p = fmaf(p, w, 0.00943887047f);
    p = fmaf(p, w, 1.00167406f);
    p = fmaf(p, w, 2.83297682f);
  }
  return p * x;
}

// ---------------- kInit: forced mask, M decay, per-spark keys --------------
__global__ void __launch_bounds__(256) kInit(const float* __restrict__ M_in,
                                             const int* __restrict__ spark_pos,
                                             const int* __restrict__ spark_age) {
  int t = threadIdx.x;
  for (int j = t; j < N; j += 256) {
    g_forced[j] = 0;
    g_Mdec[j] = __fmul_rn(M_in[j], 0.95f);
  }
  __syncthreads();

  const unsigned B0 = 0u, B1 = 42u;
  unsigned kexp0, kexp1, krand0, krand1, kcat0, kcat1;
  keypair(B0, B1, 1u, kexp0, kexp1);
  keypair(B0, B1, 2u, krand0, krand1);
  keypair(B0, B1, 3u, kcat0, kcat1);

  int i = t;
  unsigned ke0, ke1;
  keypair(kexp0, kexp1, (unsigned)i, ke0, ke1);
  g_explore[i] = (f01(bits32(ke0, ke1, 0u)) < 0.05f) ? 1 : 0;
  unsigned kr0, kr1, k20, k21;
  keypair(krand0, krand1, (unsigned)i, kr0, kr1);
  keypair(kr0, kr1, 1u, k20, k21);
  g_randpos[i] = (int)(bits32(k20, k21, 0u) & (unsigned)(N - 1));
  unsigned kc0, kc1;
  keypair(kcat0, kcat1, (unsigned)i, kc0, kc1);
  g_kc0[i] = kc0;
  g_kc1[i] = kc1;
  if (spark_age[i] < 5) g_forced[spark_pos[i]] = 1;
}

// ---------------- kMV: matvec + W decay/clip + Wc copy + state -------------
__global__ void __launch_bounds__(256) kMV(const float* __restrict__ W,
                                           const float* __restrict__ s_in,
                                           float* __restrict__ outW) {
  int r = blockIdx.x;
  const float4* w4 = (const float4*)(W + (size_t)r * N);
  const float4* s4 = (const float4*)s_in;
  float4* o4 = (float4*)(outW + (size_t)r * N);
  float4* wc4 = (float4*)(g_Wc + (size_t)r * 256);
  float acc = 0.f;
  for (int k = threadIdx.x; k < N / 4; k += 256) {
    float4 w = w4[k];
    float4 sv = s4[k];
    acc += w.x * (sv.x * 0.95f) + w.y * (sv.y * 0.95f)
         + w.z * (sv.z * 0.95f) + w.w * (sv.w * 0.95f);
    if (k < 64) wc4[k] = w;                 // original W[:,0:256] slice
    float4 o;
    o.x = fminf(fmaxf(__fmul_rn(w.x, 0.999f), -2.f), 2.f);
    o.y = fminf(fmaxf(__fmul_rn(w.y, 0.999f), -2.f), 2.f);
    o.z = fminf(fmaxf(__fmul_rn(w.z, 0.999f), -2.f), 2.f);
    o.w = fminf(fmaxf(__fmul_rn(w.w, 0.999f), -2.f), 2.f);
    o4[k] = o;
  }
  for (int off = 16; off; off >>= 1) acc += __shfl_down_sync(0xffffffffu, acc, off);
  __shared__ float sred[8];
  if ((threadIdx.x & 31) == 0) sred[threadIdx.x >> 5] = acc;
  __syncthreads();
  if (threadIdx.x == 0) {
    float a = 0.f;
    for (int w = 0; w < 8; w++) a += sred[w];
    // fused state update: noise -> sigmoid -> forced
    const unsigned B0 = 0u, B1 = 42u;
    unsigned n0, n1;
    keypair(B0, B1, 0u, n0, n1);
    const float LO = __int_as_float(0xBF7FFFFF);
    const float SQ2 = __int_as_float(0x3FB504F3);
    float f = f01(bits32(n0, n1, (unsigned)r));
    float u = fmaxf(LO, __fadd_rn(__fmul_rn(f, 2.0f), LO));
    float nrm = __fmul_rn(SQ2, erfinv_xla(u));
    float noise = __fmul_rn(0.05f, nrm);
    float x = __fadd_rn(a, noise);
    g_sState[r] = g_forced[r] ? 1.0f : (1.0f / (1.0f + expf(-x)));
  }
}

// ---------------- kGum: gumbels + {g,dv} + top-32 + wold prefetch ----------
__global__ void __launch_bounds__(1024) kGum(const float* __restrict__ W,
                                             const int* __restrict__ spark_pos) {
  extern __shared__ u64 sm_keys[];          // N keys = 64KB
  __shared__ u64 sm_red[32];
  __shared__ u64 sm_win;
  int i = blockIdx.x;
  int row = spark_pos[i];
  unsigned kc0 = g_kc0[i], kc1 = g_kc1[i];
  const float* wrow = W + (size_t)row * N;
  size_t base = (size_t)i * N;
  int tid = threadIdx.x;

  for (int j = tid; j < N; j += 1024) {
    unsigned b = bits32(kc0, kc1, (unsigned)j);
    float u = fmaxf(f01(b), 1.17549435e-38f);
    float g = -__nv_logf(-__nv_logf(u));
    float dv = divf(wrow[j]);
    float z0 = zf(g, dv, g_Mdec[j]);
    g_gd[base + j] = make_float2(g, dv);
    sm_keys[j] = packz(z0, j);
  }
  __syncthreads();

  u64 tmax = 0;
  #pragma unroll
  for (int t = 0; t < 8; t++) {
    u64 k = sm_keys[tid + t * 1024];
    if (k > tmax) tmax = k;
  }
  for (int rd = 0; rd < TOPT; rd++) {
    u64 v = tmax;
    for (int o = 16; o; o >>= 1) {
      u64 x = __shfl_down_sync(0xffffffffu, v, o);
      if (x > v) v = x;
    }
    if ((tid & 31) == 0) sm_red[tid >> 5] = v;
    __syncthreads();
    if (tid < 32) {
      u64 w = sm_red[tid];
      for (int o = 16; o; o >>= 1) {
        u64 x = __shfl_down_sync(0xffffffffu, w, o);
        if (x > w) w = x;
      }
      if (tid == 0) { sm_win = w; g_top[(size_t)i * TOPT + rd] = w; }
    }
    __syncthreads();
    u64 w = sm_win;
    if (tmax == w) {     // unique owner (keys unique)
      tmax = 0;
      #pragma unroll
      for (int t = 0; t < 8; t++) {
        int j = tid + t * 1024;
        u64 kk = sm_keys[j];
        if (kk == w) { sm_keys[j] = 0; kk = 0; }
        if (kk > tmax) tmax = kk;
      }
    }
  }
  // wold prefetch: W[cand, row] for the 32 candidates + randpos
  if (tid < TOPT) {
    u64 k = g_top[(size_t)i * TOPT + tid];
    int idx = (N - 1) - (int)(unsigned)(k & 0xffffffffu);
    g_wold[(size_t)i * 33 + tid] = W[(size_t)idx * N + row];
  } else if (tid == 32) {
    g_wold[(size_t)i * 33 + 32] = W[(size_t)g_randpos[i] * N + row];
  }
}

// ---------------- kScan: B_pre || A, slim B_post ---------------------------
// smem: s[N] M[N] pnew[N] c[N] (128KB) + top[K*32] (64KB) + small
#define SMEM_SCAN (4 * N * 4 + K * TOPT * 8 + 16 * 8 + 16 * 4 + 512 * 4 + 8 * K * 4 + 128)

__global__ void __launch_bounds__(SCAN_T) kScan(const float* __restrict__ W,
                                                const int* __restrict__ sp,
                                                const float* __restrict__ se,
                                                const int* __restrict__ sa,
                                                float* __restrict__ out) {
  extern __shared__ __align__(16) unsigned char smraw[];
  float* s_sh = (float*)smraw;
  float* M_sh = s_sh + N;
  float* pnew = M_sh + N;
  int*   c_sh = (int*)(pnew + N);
  u64*   top_sh = (u64*)(c_sh + N);   // K*TOPT
  u64*   red = top_sh + K * TOPT;     // 16
  float* redw = (float*)(red + 16);   // 16
  int*   dlist = (int*)(redw + 16);   // 512
  int*   sp_sh = dlist + 512;         // K
  int*   ex_sh = sp_sh + K;
  int*   rp_sh = ex_sh + K;
  float* edec_sh = (float*)(rp_sh + K);
  int*   reset_sh = (int*)(edec_sh + K);
  int*   res_pos = reset_sh + K;
  float* res_e = (float*)(res_pos + K);
  int*   res_age = (int*)(res_e + K);
  __shared__ int nd_sh;

  int tid = threadIdx.x;
  int lane = tid & 31;
  int wid = tid >> 5;
  const unsigned FULL = 0xffffffffu;

  for (int j = tid; j < N; j += SCAN_T) {
    s_sh[j] = g_sState[j];
    M_sh[j] = g_Mdec[j];
    c_sh[j] = 0;
    pnew[j] = 0.f;
  }
  for (int t = tid; t < K * TOPT; t += SCAN_T) top_sh[t] = g_top[t];
  if (tid < 16) { red[tid] = 0; redw[tid] = 0.f; }
  if (tid < K) {
    sp_sh[tid] = sp[tid];
    ex_sh[tid] = g_explore[tid];
    rp_sh[tid] = g_randpos[tid];
    float e = __fmul_rn(se[tid], 0.98f);
    int rs = (e < 0.05f) ? 1 : 0;
    edec_sh[tid] = e;
    reset_sh[tid] = rs;
    res_e[tid] = rs ? 1.0f : e;
    res_age[tid] = rs ? 0 : (sa[tid] + 1);
    res_pos[tid] = tid;                // reset value (i % N == i for i<256)
  }
  if (tid == 0) nd_sh = 0;
  __syncthreads();

  int nd = 0;        // dirty count valid at iteration start
  int ndpref = 0;    // slots with registers prefetched for this iteration
  float2 pre = make_float2(0.f, 0.f);
  float wdPre = 0.f;
  int idxReg = 0;
  // B-warp register double buffer of g_wold rows
  float woldC = 0.f, wrpC = 0.f, woldN = 0.f, wrpN = 0.f;
  if (wid == 0) {
    woldN = g_wold[lane];
    if (lane == 0) wrpN = g_wold[32];
  }

  for (int i = 0; i < K; i++) {
    int r = sp_sh[i];
    size_t base = (size_t)i * N;

    // B-warp registers persisting across the barrier
    u64 cnd = 0, bc = 0;
    unsigned mk = 0;
    int Lwin = 0, cidx = 0, rp = 0;
    float wcL = 0.f;
    int cpPre = 0; float pnPre = 0.f, spPre = 0.f;

    if (wid > 0) {
      // ==== A: dirty recompute + paired wold (one slot per thread) ====
      int atid = tid - 32;          // 0..511
      u64 pk = 0; float wd = 0.f;
      if (atid < nd) {
        idxReg = dlist[atid];
        float2 gd; float w0;
        if (atid < ndpref) { gd = pre; w0 = wdPre; }
        else {
          gd = g_gd[base + idxReg];                   // L1-warmed
          w0 = (r < 256) ? g_Wc[(size_t)idxReg * 256 + r]
                         : W[(size_t)idxReg * N + r];
        }
        int c = c_sh[idxReg];
        float dv = ((c & 0xffff) == (r + 1)) ? divf(pnew[idxReg]) : gd.y;
        pk = packz(zf(gd.x, dv, M_sh[idxReg]), idxReg);
        wd = w0;
      }
      for (int o = 16; o; o >>= 1) {
        u64 v = __shfl_down_sync(FULL, pk, o);
        float w2 = __shfl_down_sync(FULL, wd, o);
        if (v > pk) { pk = v; wd = w2; }
      }
      if (lane == 0) { red[wid - 1] = pk; redw[wid - 1] = wd; }
      // prefetch registers for next iteration's existing dirty slots
      if (i + 1 < K && atid < nd) {
        pre = g_gd[base + N + idxReg];
        int rn = sp_sh[i + 1];
        wdPre = (rn < 256) ? g_Wc[(size_t)idxReg * 256 + rn]
                           : W[(size_t)idxReg * N + rn];
      }
    } else {
      // ==== B_pre: everything that doesn't need the dirty max ====
      rp = rp_sh[i];
      // rotate wold register buffers + prefetch next row
      woldC = woldN; wrpC = wrpN;
      if (i + 1 < K) {
        woldN = g_wold[(size_t)(i + 1) * 33 + lane];
        if (lane == 0) wrpN = g_wold[(size_t)(i + 1) * 33 + 32];
      }
      if (lane == 0) { cpPre = c_sh[r]; pnPre = pnew[r]; spPre = s_sh[r]; }

      cnd = top_sh[i * TOPT + lane];   // sorted desc
      cidx = (N - 1) - (int)(unsigned)(cnd & 0xffffffffu);
      bool clean = !(c_sh[cidx] & BIT_LST);
      mk = __ballot_sync(FULL, clean);
      Lwin = mk ? (__ffs(mk) - 1) : 0;
      bc = __shfl_sync(FULL, cnd, Lwin);
      wcL = __shfl_sync(FULL, woldC, Lwin);

      // warm next-iter lines for potential new dirty slots
      if (i + 1 < K) {
        int rn = sp_sh[i + 1];
        warm64(&g_gd[base + N + cidx]);
        if (rn < 256) warm32(&g_Wc[(size_t)cidx * 256 + rn]);
        if (lane == 0) {
          warm64(&g_gd[base + N + r]);
          if (rn < 256) warm32(&g_Wc[(size_t)r * 256 + rn]);
        }
        if (lane == 1) {
          warm64(&g_gd[base + N + rp]);
          if (rn < 256) warm32(&g_Wc[(size_t)rp * 256 + rn]);
        }
      }
    }
    int ndpref_next = nd;
    __syncthreads();

    // ==== B_post: combine dirty max with clean candidate; lane 0 updates ====
    if (wid == 0) {
      u64 dmax = 0; float dwold = 0.f;
      if (lane < 16) { dmax = red[lane]; dwold = redw[lane]; }
      for (int o = 16; o; o >>= 1) {
        u64 v = __shfl_xor_sync(FULL, dmax, o);
        float w2 = __shfl_xor_sync(FULL, dwold, o);
        if (v > dmax) { dmax = v; dwold = w2; }
      }

      u64 best;
      bool cleanWin = false;
      bool fbWin = false;
      if (mk) {
        if (dmax > bc) { best = dmax; } else { best = bc; cleanWin = true; }
      } else {
        u64 last = __shfl_sync(FULL, cnd, TOPT - 1);
        if (dmax > last) {
          best = dmax;                     // clean max <= last < dmax
        } else {
          // exact full-row fallback (not expected to trigger)
          u64 fb = 0;
          for (int j = lane; j < N; j += 32) {
            int c = c_sh[j];
            float2 gd = g_gd[base + j];
            float dv = ((c & 0xffff) == (r + 1)) ? divf(pnew[j]) : gd.y;
            u64 p2 = packz(zf(gd.x, dv, M_sh[j]), j);
            if (p2 > fb) fb = p2;
          }
          for (int o = 16; o; o >>= 1) {
            u64 v = __shfl_xor_sync(FULL, fb, o);
            if (v > fb) fb = v;
          }
          best = fb;
          fbWin = true;
        }
      }

      if (lane == 0) {
        int cat = (N - 1) - (int)(unsigned)(best & 0xffffffffu);
        int ex = ex_sh[i];
        int nxt = ex ? rp : cat;
        int prev = r;
        int cp = cpPre;
        float wold;
        if ((cp & 0xffff) == (nxt + 1)) {
          wold = pnPre;
        } else if (ex) {
          wold = wrpC;
        } else if (fbWin) {
          wold = (prev < 256) ? g_Wc[(size_t)nxt * 256 + prev]
                              : W[(size_t)nxt * N + prev];
        } else if (cleanWin) {
          wold = wcL;
        } else {
          wold = dwold;                    // dirty winner's paired wold
        }
        pnew[prev] = __fadd_rn(__fmul_rn(wold, 0.95f),
                               __fmul_rn(spPre, 0.05f));
        int ndl = nd;
        int ncp = (cp & ~0xffff) | (nxt + 1);
        if (!(cp & BIT_LST)) { dlist[ndl] = prev; ndl++; ncp |= BIT_LST; }
        c_sh[prev] = ncp;
        int cn = (nxt == prev) ? ncp : c_sh[nxt];
        M_sh[nxt] = __fadd_rn(M_sh[nxt], 0.2f);
        int ncn = cn | BIT_DEP;
        if (!(cn & BIT_LST)) { dlist[ndl] = nxt; ndl++; ncn |= BIT_LST; }
        c_sh[nxt] = ncn;
        s_sh[nxt] = edec_sh[i];
        if (!reset_sh[i]) res_pos[i] = nxt;
        nd_sh = ndl;
      }
    }
    __syncthreads();
    nd = nd_sh;
    ndpref = ndpref_next;
  }

  // epilogue: outputs (layout: pos[K], W[N*N], s[N], M[N], energy[K], age[K])
  const size_t OUT_W = K;
  const size_t OUT_S = OUT_W + (size_t)N * N;
  const size_t OUT_M = OUT_S + N;
  const size_t OUT_E = OUT_M + N;
  const size_t OUT_A = OUT_E + K;
  for (int j = tid; j < N; j += SCAN_T) {
    out[OUT_S + j] = s_sh[j];
    out[OUT_M + j] = M_sh[j];
    int c = c_sh[j];
    int prow = c & 0xffff;
    if (prow) {
      size_t idx = (size_t)(prow - 1) * N + (size_t)j;
      out[OUT_W + idx] = fminf(fmaxf(__fmul_rn(pnew[j], 0.999f), -2.f), 2.f);
    }
  }
  for (int i2 = tid; i2 < K; i2 += SCAN_T) {
    out[i2] = (float)res_pos[i2];
    out[OUT_E + i2] = res_e[i2];
    out[OUT_A + i2] = (float)res_age[i2];
  }
}

// ---------------- launch ----------------
extern "C" void kernel_launch(void* const* d_in, const int* in_sizes, int n_in,
                              void* d_out, int out_size) {
  const float* W = (const float*)d_in[0];
  const float* s = (const float*)d_in[1];
  const float* M = (const float*)d_in[2];
  const int* sp = (const int*)d_in[3];
  const float* se = (const float*)d_in[4];
  const int* sa = (const int*)d_in[5];
  float* out = (float*)d_out;

  cudaFuncSetAttribute(kGum, cudaFuncAttributeMaxDynamicSharedMemorySize,
                       N * 8);
  cudaFuncSetAttribute(kScan, cudaFuncAttributeMaxDynamicSharedMemorySize,
                       SMEM_SCAN);

  kInit<<<1, 256>>>(M, sp, sa);
  kMV<<<N, 256>>>(W, s, out + K);      // out_W starts right after pos[K]
  kGum<<<K, 1024, N * 8>>>(W, sp);
  kScan<<<1, SCAN_T, SMEM_SCAN>>>(W, sp, se, sa, out);
}